// round 16
// baseline (speedup 1.0000x reference)
#include <cuda_runtime.h>
#include <cuda_fp16.h>
#include <cstddef>
#include <cstdint>
#include <math.h>

// Problem constants
#define BB 4
#define LSEQ 2048
#define DMODEL 1024
#define NH 16
#define HDIM 64
#define MROWS (BB * LSEQ)      // 8192
#define QKVN (3 * DMODEL)      // 3072

// Scratch (static device arrays; no allocation APIs allowed)
__device__ __half g_x_h[(size_t)MROWS * DMODEL];
__device__ __half g_wqkvT_h[(size_t)QKVN * DMODEL];   // (3072,1024) K-major
__device__ __half g_wprojT_h[(size_t)DMODEL * DMODEL];
__device__ __half g_qkv_h[(size_t)MROWS * QKVN];
__device__ __half g_attn_h[(size_t)MROWS * DMODEL];

// ---- fp16 MMA m16n8k16, fp32 accumulate ----------------------------------
__device__ __forceinline__ void mma_f16(float* d, const uint32_t* a,
                                        const uint32_t* b) {
    asm volatile(
        "mma.sync.aligned.m16n8k16.row.col.f32.f16.f16.f32 "
        "{%0,%1,%2,%3}, {%4,%5,%6,%7}, {%8,%9}, {%0,%1,%2,%3};\n"
        : "+f"(d[0]), "+f"(d[1]), "+f"(d[2]), "+f"(d[3])
        : "r"(a[0]), "r"(a[1]), "r"(a[2]), "r"(a[3]), "r"(b[0]), "r"(b[1]));
}

__device__ __forceinline__ void ldsm_x4(uint32_t* r, uint32_t addr) {
    asm volatile(
        "ldmatrix.sync.aligned.m8n8.x4.shared.b16 {%0,%1,%2,%3}, [%4];"
        : "=r"(r[0]), "=r"(r[1]), "=r"(r[2]), "=r"(r[3]) : "r"(addr));
}
__device__ __forceinline__ void ldsm_x4_t(uint32_t* r, uint32_t addr) {
    asm volatile(
        "ldmatrix.sync.aligned.m8n8.x4.trans.shared.b16 {%0,%1,%2,%3}, [%4];"
        : "=r"(r[0]), "=r"(r[1]), "=r"(r[2]), "=r"(r[3]) : "r"(addr));
}

__device__ __forceinline__ void cpa16(uint32_t dst_smem, const void* src) {
    asm volatile("cp.async.cg.shared.global [%0], [%1], 16;\n"
                 :: "r"(dst_smem), "l"(src));
}
__device__ __forceinline__ void cpa_commit() {
    asm volatile("cp.async.commit_group;\n");
}
template <int N>
__device__ __forceinline__ void cpa_wait() {
    asm volatile("cp.async.wait_group %0;\n" :: "n"(N));
}
__device__ __forceinline__ uint32_t smem_u32(const void* p) {
    return (uint32_t)__cvta_generic_to_shared(p);
}
__device__ __forceinline__ uint32_t packh2(float lo, float hi) {
    __half2 h = __floats2half2_rn(lo, hi);
    return *reinterpret_cast<uint32_t*>(&h);
}

// ---------------------------------------------------------------------------
// Pre-pass kernels: fp32 -> fp16 convert / transpose
// ---------------------------------------------------------------------------
__global__ void f2h_kernel(const float4* __restrict__ in,
                           uint2* __restrict__ out, int n4)
{
    int i = blockIdx.x * blockDim.x + threadIdx.x;
    if (i < n4) {
        float4 v = in[i];
        out[i] = make_uint2(packh2(v.x, v.y), packh2(v.z, v.w));
    }
}

// in (R, C) fp32 -> out (C, R) fp16
__global__ void transpose_h_kernel(const float* __restrict__ in,
                                   __half* __restrict__ out, int R, int C)
{
    __shared__ float tile[32][33];
    int gx = blockIdx.x * 32, gy = blockIdx.y * 32;
    int tx = threadIdx.x, ty = threadIdx.y;
#pragma unroll
    for (int j = 0; j < 4; j++)
        tile[ty + j * 8][tx] = in[(size_t)(gy + ty + j * 8) * C + gx + tx];
    __syncthreads();
#pragma unroll
    for (int j = 0; j < 4; j++)
        out[(size_t)(gx + ty + j * 8) * R + gy + tx] =
            __float2half(tile[tx][ty + j * 8]);
}

// ---------------------------------------------------------------------------
// fp16 tensor-core GEMM: C[M,N] = A[M,K] @ BT[N,K]^T (+bias).
// CTA tile 128x128, BK=64 halves (144B rows, ldmatrix conflict-free),
// FOUR warps (2M x 2N), warp tile 64x64 -> 4 MMAs per ldmatrix.
// 3-stage cp.async pipeline, 2 CTAs/SM: two independent barrier domains
// interleave so one CTA's sync never idles the whole SM.
// ---------------------------------------------------------------------------
#define HSTR 72
#define GNSTG 3
#define GSTAGE_BYTES (256 * HSTR * 2)   // 36864
#define GEMM_SMEM_BYTES (GNSTG * GSTAGE_BYTES)

__global__ void __launch_bounds__(128, 2)
gemm_f16_kernel(const __half* __restrict__ A, const __half* __restrict__ BT,
                float* __restrict__ Cf, __half* __restrict__ Ch,
                int M, int N, int K, const float* __restrict__ bias)
{
    extern __shared__ char gsm[];
    const uint32_t smb = smem_u32(gsm);

    const int tid = threadIdx.x;
    const int lane = tid & 31;
    const int warp = tid >> 5;           // 0..3
    const int wm = (warp & 1) * 64;      // warp M offset
    const int wn = (warp >> 1) * 64;     // warp N offset
    const int g = lane >> 2;
    const int t = lane & 3;

    const __half* Ab  = A  + (size_t)blockIdx.y * 128 * K;
    const __half* BTb = BT + (size_t)blockIdx.x * 128 * K;

    // A: 128 rows x 8 chunks = 1024 -> 8/thread at 128 threads; B same.
    auto load_stage = [&](int s, int k0) {
        uint32_t sa = smb + (uint32_t)(s * GSTAGE_BYTES);
        uint32_t sb = sa + 128u * 144u;
#pragma unroll
        for (int p = 0; p < 8; p++) {
            int idx = tid + p * 128;
            int r = idx >> 3, c16 = idx & 7;
            cpa16(sa + (uint32_t)(r * 144 + c16 * 16),
                  Ab + (size_t)r * K + k0 + c16 * 8);
        }
#pragma unroll
        for (int p = 0; p < 8; p++) {
            int idx = tid + p * 128;
            int r = idx >> 3, c16 = idx & 7;
            cpa16(sb + (uint32_t)(r * 144 + c16 * 16),
                  BTb + (size_t)r * K + k0 + c16 * 8);
        }
        cpa_commit();
    };

    // ldmatrix per-lane byte offsets
    uint32_t a_off[4];
#pragma unroll
    for (int mi = 0; mi < 4; mi++)
        a_off[mi] = (uint32_t)(((wm + mi * 16 + (lane & 15)) * HSTR +
                                ((lane >> 4) << 3)) * 2);
    uint32_t b_off[4];
#pragma unroll
    for (int nip = 0; nip < 4; nip++)
        b_off[nip] = (uint32_t)(((wn + nip * 16 + ((lane >> 4) << 3) +
                                  (lane & 7)) * HSTR +
                                 (((lane >> 3) & 1) << 3)) * 2);

    float acc[4][8][4];
#pragma unroll
    for (int mi = 0; mi < 4; mi++)
#pragma unroll
        for (int ni = 0; ni < 8; ni++)
#pragma unroll
            for (int q = 0; q < 4; q++) acc[mi][ni][q] = 0.f;

    const int NIT = K / 64;
    load_stage(0, 0);
    load_stage(1, 64);

    int stg = 0;
    for (int it = 0; it < NIT; it++) {
        if (it + 1 < NIT) cpa_wait<1>(); else cpa_wait<0>();
        __syncthreads();
        if (it + 2 < NIT) load_stage((stg + 2) % GNSTG, (it + 2) * 64);

        const uint32_t sa = smb + (uint32_t)(stg * GSTAGE_BYTES);
        const uint32_t sb = sa + 128u * 144u;

#pragma unroll
        for (int ks = 0; ks < 4; ks++) {
            const uint32_t khb = (uint32_t)(ks * 16 * 2);
            uint32_t af[4][4];
#pragma unroll
            for (int mi = 0; mi < 4; mi++)
                ldsm_x4(af[mi], sa + a_off[mi] + khb);
            uint32_t bf[4][4];
#pragma unroll
            for (int nip = 0; nip < 4; nip++)
                ldsm_x4(bf[nip], sb + b_off[nip] + khb);
#pragma unroll
            for (int mi = 0; mi < 4; mi++)
#pragma unroll
                for (int nip = 0; nip < 4; nip++) {
                    mma_f16(acc[mi][2 * nip],     af[mi], bf[nip]);
                    mma_f16(acc[mi][2 * nip + 1], af[mi], bf[nip] + 2);
                }
        }
        stg = (stg + 1) % GNSTG;
    }

    const int row0 = blockIdx.y * 128 + wm;
    const int col0 = blockIdx.x * 128 + wn;
#pragma unroll
    for (int mi = 0; mi < 4; mi++) {
        int r = row0 + mi * 16 + g;
#pragma unroll
        for (int ni = 0; ni < 8; ni++) {
            int c = col0 + ni * 8 + t * 2;
            if (Ch) {
                *reinterpret_cast<uint32_t*>(Ch + (size_t)r * N + c) =
                    packh2(acc[mi][ni][0], acc[mi][ni][1]);
                *reinterpret_cast<uint32_t*>(Ch + (size_t)(r + 8) * N + c) =
                    packh2(acc[mi][ni][2], acc[mi][ni][3]);
            } else {
                float b0 = 0.f, b1 = 0.f;
                if (bias) { b0 = bias[c]; b1 = bias[c + 1]; }
                *reinterpret_cast<float2*>(Cf + (size_t)r * N + c) =
                    make_float2(acc[mi][ni][0] + b0, acc[mi][ni][1] + b1);
                *reinterpret_cast<float2*>(Cf + (size_t)(r + 8) * N + c) =
                    make_float2(acc[mi][ni][2] + b0, acc[mi][ni][3] + b1);
            }
        }
    }
}

// ---------------------------------------------------------------------------
// fp16 flash attention (unchanged from round 15 — current best).
// Q-tile 128, KV-tile 64, 8 warps; P register-resident; ldmatrix everywhere;
// 3-stage KV ring, one barrier per KV tile, prefetch distance 2.
// ---------------------------------------------------------------------------
#define ASTRH 72
#define BLKQ 128
#define KVSTG_BYTES (2 * 64 * ASTRH * 2)   // K+V per stage = 18432
#define KVNSTG 3
#define ATTN_SMEM_BYTES (BLKQ * ASTRH * 2 + KVNSTG * KVSTG_BYTES)

__global__ void __launch_bounds__(256)
attn_f16_kernel(const __half* __restrict__ qkv, __half* __restrict__ out)
{
    extern __shared__ char asm_[];
    __half* sQ = (__half*)asm_;
    const uint32_t sQb  = smem_u32(sQ);
    const uint32_t sKVb = sQb + BLKQ * ASTRH * 2;

    const int tid = threadIdx.x;
    const int lane = tid & 31;
    const int warp = tid >> 5;
    const int g = lane >> 2;
    const int t = lane & 3;
    const int m0 = warp * 16;

    const int qt = (int)(gridDim.x - 1) - (int)blockIdx.x;  // heavy first
    const int bh = blockIdx.y;
    const int b = bh >> 4, h = bh & 15;
    const __half* base = qkv + (size_t)b * LSEQ * QKVN + h * HDIM;
    const int q0 = qt * BLKQ;
    const int nkv = 2 * qt + 2;

    auto load_kv = [&](int kt, int stg) {
        uint32_t kb = sKVb + (uint32_t)(stg * KVSTG_BYTES);
        uint32_t vb = kb + 64u * ASTRH * 2u;
        const int k0 = kt * 64;
#pragma unroll
        for (int p = 0; p < 2; p++) {
            int idx = tid + p * 256;
            int r = idx >> 3, c16 = idx & 7;
            const __half* rp = base + (size_t)(k0 + r) * QKVN + c16 * 8;
            cpa16(kb + (uint32_t)(r * 144 + c16 * 16), rp + DMODEL);
            cpa16(vb + (uint32_t)(r * 144 + c16 * 16), rp + 2 * DMODEL);
        }
        cpa_commit();
    };

    // Q load (own group), then KV stages 0 and 1
#pragma unroll
    for (int p = 0; p < 4; p++) {
        int idx = tid + p * 256;
        int r = idx >> 3, c16 = idx & 7;
        cpa16(sQb + (uint32_t)(r * 144 + c16 * 16),
              base + (size_t)(q0 + r) * QKVN + c16 * 8);
    }
    cpa_commit();
    load_kv(0, 0);
    if (nkv > 1) load_kv(1, 1);

    if (nkv > 1) cpa_wait<2>(); else cpa_wait<1>();   // Q landed
    __syncthreads();

    // Hoist Q fragments via ldmatrix, then scale by 0.125 (exact in fp16)
    uint32_t aq[4][4];
    {
        uint32_t q_off = (uint32_t)(((m0 + (lane & 15)) * ASTRH +
                                     ((lane >> 4) << 3)) * 2);
        const __half2 sc = __float2half2_rn(0.125f);
#pragma unroll
        for (int ks = 0; ks < 4; ks++) {
            ldsm_x4(aq[ks], sQb + q_off + (uint32_t)(ks * 16 * 2));
#pragma unroll
            for (int q = 0; q < 4; q++) {
                __half2 v = __hmul2(*reinterpret_cast<__half2*>(&aq[ks][q]), sc);
                aq[ks][q] = *reinterpret_cast<uint32_t*>(&v);
            }
        }
    }

    // K-fragment ldmatrix lane offset
    uint32_t k_off[4];
#pragma unroll
    for (int nip = 0; nip < 4; nip++)
        k_off[nip] = (uint32_t)(((nip * 16 + ((lane >> 4) << 3) +
                                  (lane & 7)) * ASTRH +
                                 (((lane >> 3) & 1) << 3)) * 2);

    float o[8][4];
#pragma unroll
    for (int nt = 0; nt < 8; nt++)
#pragma unroll
        for (int q = 0; q < 4; q++) o[nt][q] = 0.f;
    float mr0 = -1e30f, mr1 = -1e30f, l0 = 0.f, l1 = 0.f;

    const int row0g = q0 + m0 + g;
    const int row1g = row0g + 8;

    int stg = 0;
    for (int kt = 0; kt < nkv; kt++) {
        const int k0 = kt * 64;
        if (kt + 1 < nkv) cpa_wait<1>(); else cpa_wait<0>();
        __syncthreads();
        if (kt + 2 < nkv) load_kv(kt + 2, (stg + 2) % KVNSTG);

        const uint32_t kvb = sKVb + (uint32_t)(stg * KVSTG_BYTES);
        const uint32_t sVb = kvb + 64u * ASTRH * 2u;

        // S = (Q*scale) @ K^T : 16x64 per warp, 32 MMAs
        float s[8][4];
#pragma unroll
        for (int nt = 0; nt < 8; nt++)
#pragma unroll
            for (int q = 0; q < 4; q++) s[nt][q] = 0.f;

#pragma unroll
        for (int ks = 0; ks < 4; ks++) {
            const uint32_t khb = (uint32_t)(ks * 16 * 2);
#pragma unroll
            for (int nip = 0; nip < 4; nip++) {
                uint32_t bf[4];
                ldsm_x4(bf, kvb + k_off[nip] + khb);
                mma_f16(s[2 * nip],     aq[ks], bf);
                mma_f16(s[2 * nip + 1], aq[ks], bf + 2);
            }
        }

        // Causal mask (diagonal tiles only)
        if (kt >= 2 * qt) {
#pragma unroll
            for (int nt = 0; nt < 8; nt++) {
                int cb = k0 + nt * 8 + 2 * t;
#pragma unroll
                for (int q = 0; q < 2; q++) {
                    if (cb + q > row0g) s[nt][q] = -1e30f;
                    if (cb + q > row1g) s[nt][2 + q] = -1e30f;
                }
            }
        }

        // Online softmax (rows g and g+8; quad-reduce over t lanes)
        float mt0 = -1e30f, mt1 = -1e30f;
#pragma unroll
        for (int nt = 0; nt < 8; nt++) {
            mt0 = fmaxf(mt0, fmaxf(s[nt][0], s[nt][1]));
            mt1 = fmaxf(mt1, fmaxf(s[nt][2], s[nt][3]));
        }
        mt0 = fmaxf(mt0, __shfl_xor_sync(0xffffffffu, mt0, 1));
        mt0 = fmaxf(mt0, __shfl_xor_sync(0xffffffffu, mt0, 2));
        mt1 = fmaxf(mt1, __shfl_xor_sync(0xffffffffu, mt1, 1));
        mt1 = fmaxf(mt1, __shfl_xor_sync(0xffffffffu, mt1, 2));

        float mn0 = fmaxf(mr0, mt0), mn1 = fmaxf(mr1, mt1);
        float cr0 = __expf(mr0 - mn0), cr1 = __expf(mr1 - mn1);
        mr0 = mn0; mr1 = mn1;

        float rs0 = 0.f, rs1 = 0.f;
#pragma unroll
        for (int nt = 0; nt < 8; nt++) {
            s[nt][0] = __expf(s[nt][0] - mn0);
            s[nt][1] = __expf(s[nt][1] - mn0);
            s[nt][2] = __expf(s[nt][2] - mn1);
            s[nt][3] = __expf(s[nt][3] - mn1);
            rs0 += s[nt][0] + s[nt][1];
            rs1 += s[nt][2] + s[nt][3];
        }
        rs0 += __shfl_xor_sync(0xffffffffu, rs0, 1);
        rs0 += __shfl_xor_sync(0xffffffffu, rs0, 2);
        rs1 += __shfl_xor_sync(0xffffffffu, rs1, 1);
        rs1 += __shfl_xor_sync(0xffffffffu, rs1, 2);
        l0 = l0 * cr0 + rs0;
        l1 = l1 * cr1 + rs1;

#pragma unroll
        for (int nt = 0; nt < 8; nt++) {
            o[nt][0] *= cr0; o[nt][1] *= cr0;
            o[nt][2] *= cr1; o[nt][3] *= cr1;
        }

        // Pack P fragments in registers
        uint32_t ap[4][4];
#pragma unroll
        for (int ks = 0; ks < 4; ks++) {
            ap[ks][0] = packh2(s[2 * ks][0], s[2 * ks][1]);
            ap[ks][1] = packh2(s[2 * ks][2], s[2 * ks][3]);
            ap[ks][2] = packh2(s[2 * ks + 1][0], s[2 * ks + 1][1]);
            ap[ks][3] = packh2(s[2 * ks + 1][2], s[2 * ks + 1][3]);
        }

        // O += P @ V, V frags via ldmatrix.x4.trans
#pragma unroll
        for (int ks = 0; ks < 4; ks++) {
#pragma unroll
            for (int ntp = 0; ntp < 4; ntp++) {
                uint32_t bv[4];
                uint32_t vaddr = sVb +
                    (uint32_t)(((16 * ks + (lane & 15)) * ASTRH +
                                ntp * 16 + ((lane >> 4) << 3)) * 2);
                ldsm_x4_t(bv, vaddr);
                mma_f16(o[2 * ntp],     ap[ks], bv);
                mma_f16(o[2 * ntp + 1], ap[ks], bv + 2);
            }
        }
        stg = (stg + 1) % KVNSTG;
    }

    // Epilogue: normalize, write fp16 (B*L, D)
    float inv0 = 1.0f / l0, inv1 = 1.0f / l1;
    __half* ob0 = out + (size_t)(b * LSEQ + row0g) * DMODEL + h * HDIM + 2 * t;
    __half* ob1 = out + (size_t)(b * LSEQ + row1g) * DMODEL + h * HDIM + 2 * t;
#pragma unroll
    for (int nt = 0; nt < 8; nt++) {
        *reinterpret_cast<uint32_t*>(ob0 + nt * 8) =
            packh2(o[nt][0] * inv0, o[nt][1] * inv0);
        *reinterpret_cast<uint32_t*>(ob1 + nt * 8) =
            packh2(o[nt][2] * inv1, o[nt][3] * inv1);
    }
}

// ---------------------------------------------------------------------------
extern "C" void kernel_launch(void* const* d_in, const int* in_sizes, int n_in,
                              void* d_out, int out_size)
{
    (void)in_sizes; (void)n_in; (void)out_size;
    const float* x      = (const float*)d_in[0];
    // d_in[1] = attn_mask (always causal triu(k=1); implemented directly)
    const float* w_qkv  = (const float*)d_in[2];
    const float* w_proj = (const float*)d_in[3];
    const float* b_proj = (const float*)d_in[4];
    float* out = (float*)d_out;

    __half *xh, *wqkvT, *wprojT, *qkvh, *attnh;
    cudaGetSymbolAddress((void**)&xh, g_x_h);
    cudaGetSymbolAddress((void**)&wqkvT, g_wqkvT_h);
    cudaGetSymbolAddress((void**)&wprojT, g_wprojT_h);
    cudaGetSymbolAddress((void**)&qkvh, g_qkv_h);
    cudaGetSymbolAddress((void**)&attnh, g_attn_h);

    cudaFuncSetAttribute(gemm_f16_kernel,
                         cudaFuncAttributeMaxDynamicSharedMemorySize,
                         GEMM_SMEM_BYTES);
    cudaFuncSetAttribute(attn_f16_kernel,
                         cudaFuncAttributeMaxDynamicSharedMemorySize,
                         ATTN_SMEM_BYTES);

    // 0) Pre-pass: fp16 convert x; transpose+convert weights to [N][K]
    {
        int n4x = MROWS * DMODEL / 4;
        f2h_kernel<<<(n4x + 255) / 256, 256>>>(
            (const float4*)x, (uint2*)xh, n4x);
        dim3 tb(32, 8);
        transpose_h_kernel<<<dim3(QKVN / 32, DMODEL / 32), tb>>>(
            w_qkv, wqkvT, DMODEL, QKVN);
        transpose_h_kernel<<<dim3(DMODEL / 32, DMODEL / 32), tb>>>(
            w_proj, wprojT, DMODEL, DMODEL);
    }

    // 1) QKV GEMM: (8192,1024) @ (1024,3072), fp16 out
    {
        dim3 grid(QKVN / 128, MROWS / 128);
        gemm_f16_kernel<<<grid, 128, GEMM_SMEM_BYTES>>>(
            xh, wqkvT, nullptr, qkvh, MROWS, QKVN, DMODEL, nullptr);
    }
    // 2) Causal flash attention (fp16 MMA, register P, 3-stage KV pipeline)
    {
        dim3 grid(LSEQ / BLKQ, BB * NH);
        attn_f16_kernel<<<grid, 256, ATTN_SMEM_BYTES>>>(qkvh, attnh);
    }
    // 3) Output projection + bias: (8192,1024) @ (1024,1024), fp32 out
    {
        dim3 grid(DMODEL / 128, MROWS / 128);
        gemm_f16_kernel<<<grid, 128, GEMM_SMEM_BYTES>>>(
            attnh, wprojT, out, nullptr, MROWS, DMODEL, DMODEL, b_proj);
    }
}

// round 17
// speedup vs baseline: 1.0342x; 1.0342x over previous
#include <cuda_runtime.h>
#include <cuda_fp16.h>
#include <cstddef>
#include <cstdint>
#include <math.h>

// Problem constants
#define BB 4
#define LSEQ 2048
#define DMODEL 1024
#define NH 16
#define HDIM 64
#define MROWS (BB * LSEQ)      // 8192
#define QKVN (3 * DMODEL)      // 3072

// Scratch (static device arrays; no allocation APIs allowed)
__device__ __half g_x_h[(size_t)MROWS * DMODEL];
__device__ __half g_wqkvT_h[(size_t)QKVN * DMODEL];   // (3072,1024) K-major
__device__ __half g_wprojT_h[(size_t)DMODEL * DMODEL];
__device__ __half g_qkv_h[(size_t)MROWS * QKVN];
__device__ __half g_attn_h[(size_t)MROWS * DMODEL];

// ---- fp16 MMA m16n8k16, fp32 accumulate ----------------------------------
__device__ __forceinline__ void mma_f16(float* d, const uint32_t* a,
                                        const uint32_t* b) {
    asm volatile(
        "mma.sync.aligned.m16n8k16.row.col.f32.f16.f16.f32 "
        "{%0,%1,%2,%3}, {%4,%5,%6,%7}, {%8,%9}, {%0,%1,%2,%3};\n"
        : "+f"(d[0]), "+f"(d[1]), "+f"(d[2]), "+f"(d[3])
        : "r"(a[0]), "r"(a[1]), "r"(a[2]), "r"(a[3]), "r"(b[0]), "r"(b[1]));
}

__device__ __forceinline__ void ldsm_x4(uint32_t* r, uint32_t addr) {
    asm volatile(
        "ldmatrix.sync.aligned.m8n8.x4.shared.b16 {%0,%1,%2,%3}, [%4];"
        : "=r"(r[0]), "=r"(r[1]), "=r"(r[2]), "=r"(r[3]) : "r"(addr));
}
__device__ __forceinline__ void ldsm_x4_t(uint32_t* r, uint32_t addr) {
    asm volatile(
        "ldmatrix.sync.aligned.m8n8.x4.trans.shared.b16 {%0,%1,%2,%3}, [%4];"
        : "=r"(r[0]), "=r"(r[1]), "=r"(r[2]), "=r"(r[3]) : "r"(addr));
}

__device__ __forceinline__ void cpa16(uint32_t dst_smem, const void* src) {
    asm volatile("cp.async.cg.shared.global [%0], [%1], 16;\n"
                 :: "r"(dst_smem), "l"(src));
}
__device__ __forceinline__ void cpa_commit() {
    asm volatile("cp.async.commit_group;\n");
}
template <int N>
__device__ __forceinline__ void cpa_wait() {
    asm volatile("cp.async.wait_group %0;\n" :: "n"(N));
}
__device__ __forceinline__ uint32_t smem_u32(const void* p) {
    return (uint32_t)__cvta_generic_to_shared(p);
}
__device__ __forceinline__ uint32_t packh2(float lo, float hi) {
    __half2 h = __floats2half2_rn(lo, hi);
    return *reinterpret_cast<uint32_t*>(&h);
}

// ---------------------------------------------------------------------------
// Fused pre-pass: one launch does (a) x fp32->fp16, (b) w_qkv transpose+cvt,
// (c) w_proj transpose+cvt. Job decoded from a 1-D grid.
//   blocks [0, NB_X)                 : f2h of x (256 float4 per block)
//   blocks [NB_X, NB_X+NB_WQ)        : 32x32 transpose tiles of w_qkv
//   blocks [NB_X+NB_WQ, +NB_WP)      : 32x32 transpose tiles of w_proj
// ---------------------------------------------------------------------------
#define N4X   (MROWS * DMODEL / 4)          // 2097152
#define NB_X  (N4X / 256)                   // 8192
#define WQ_TX (QKVN / 32)                   // 96 tiles in x
#define WQ_TY (DMODEL / 32)                 // 32 tiles in y
#define NB_WQ (WQ_TX * WQ_TY)               // 3072
#define WP_T  (DMODEL / 32)                 // 32
#define NB_WP (WP_T * WP_T)                 // 1024

__global__ void __launch_bounds__(256)
prepass_kernel(const float* __restrict__ x, __half* __restrict__ xh,
               const float* __restrict__ wqkv, __half* __restrict__ wqkvT,
               const float* __restrict__ wproj, __half* __restrict__ wprojT)
{
    __shared__ float tile[32][33];
    const int bid = blockIdx.x;
    const int tid = threadIdx.x;

    if (bid < NB_X) {
        int i = bid * 256 + tid;
        float4 v = reinterpret_cast<const float4*>(x)[i];
        reinterpret_cast<uint2*>(xh)[i] =
            make_uint2(packh2(v.x, v.y), packh2(v.z, v.w));
        return;
    }

    // Transpose job: in (R,C) fp32 -> out (C,R) fp16, 32x32 tile
    const float* in;
    __half* outp;
    int R, C, tx_tiles, tb;
    if (bid < NB_X + NB_WQ) {
        in = wqkv; outp = wqkvT; R = DMODEL; C = QKVN;
        tx_tiles = WQ_TX; tb = bid - NB_X;
    } else {
        in = wproj; outp = wprojT; R = DMODEL; C = DMODEL;
        tx_tiles = WP_T; tb = bid - NB_X - NB_WQ;
    }
    int gx = (tb % tx_tiles) * 32;
    int gy = (tb / tx_tiles) * 32;
    int tx = tid & 31, ty = tid >> 5;   // (32, 8)
#pragma unroll
    for (int j = 0; j < 4; j++)
        tile[ty + j * 8][tx] = in[(size_t)(gy + ty + j * 8) * C + gx + tx];
    __syncthreads();
#pragma unroll
    for (int j = 0; j < 4; j++)
        outp[(size_t)(gx + ty + j * 8) * R + gy + tx] =
            __float2half(tile[tx][ty + j * 8]);
}

// ---------------------------------------------------------------------------
// fp16 tensor-core GEMM (ROUND-15 CONFIG — best measured):
// CTA tile 128x128, BK=64 halves (144B rows, ldmatrix conflict-free),
// 8 warps (4M x 2N), warp tile 32x64, 3-stage cp.async pipeline,
// 2 CTAs/SM, one barrier per k-iter.
// ---------------------------------------------------------------------------
#define HSTR 72
#define GNSTG 3
#define GSTAGE_BYTES (256 * HSTR * 2)   // 36864
#define GEMM_SMEM_BYTES (GNSTG * GSTAGE_BYTES)

__global__ void __launch_bounds__(256, 2)
gemm_f16_kernel(const __half* __restrict__ A, const __half* __restrict__ BT,
                float* __restrict__ Cf, __half* __restrict__ Ch,
                int M, int N, int K, const float* __restrict__ bias)
{
    extern __shared__ char gsm[];
    const uint32_t smb = smem_u32(gsm);

    const int tid = threadIdx.x;
    const int lane = tid & 31;
    const int warp = tid >> 5;
    const int wm = (warp & 3) * 32;
    const int wn = (warp >> 2) * 64;
    const int g = lane >> 2;
    const int t = lane & 3;

    const __half* Ab  = A  + (size_t)blockIdx.y * 128 * K;
    const __half* BTb = BT + (size_t)blockIdx.x * 128 * K;

    auto load_stage = [&](int s, int k0) {
        uint32_t sa = smb + (uint32_t)(s * GSTAGE_BYTES);
        uint32_t sb = sa + 128u * 144u;
#pragma unroll
        for (int p = 0; p < 4; p++) {
            int idx = tid + p * 256;
            int r = idx >> 3, c16 = idx & 7;
            cpa16(sa + (uint32_t)(r * 144 + c16 * 16),
                  Ab + (size_t)r * K + k0 + c16 * 8);
        }
#pragma unroll
        for (int p = 0; p < 4; p++) {
            int idx = tid + p * 256;
            int r = idx >> 3, c16 = idx & 7;
            cpa16(sb + (uint32_t)(r * 144 + c16 * 16),
                  BTb + (size_t)r * K + k0 + c16 * 8);
        }
        cpa_commit();
    };

    uint32_t a_off[2];
#pragma unroll
    for (int mi = 0; mi < 2; mi++)
        a_off[mi] = (uint32_t)(((wm + mi * 16 + (lane & 15)) * HSTR +
                                ((lane >> 4) << 3)) * 2);
    uint32_t b_off[4];
#pragma unroll
    for (int nip = 0; nip < 4; nip++)
        b_off[nip] = (uint32_t)(((wn + nip * 16 + ((lane >> 4) << 3) +
                                  (lane & 7)) * HSTR +
                                 (((lane >> 3) & 1) << 3)) * 2);

    float acc[2][8][4];
#pragma unroll
    for (int mi = 0; mi < 2; mi++)
#pragma unroll
        for (int ni = 0; ni < 8; ni++)
#pragma unroll
            for (int q = 0; q < 4; q++) acc[mi][ni][q] = 0.f;

    const int NIT = K / 64;
    load_stage(0, 0);
    load_stage(1, 64);

    int stg = 0;
    for (int it = 0; it < NIT; it++) {
        if (it + 1 < NIT) cpa_wait<1>(); else cpa_wait<0>();
        __syncthreads();
        if (it + 2 < NIT) load_stage((stg + 2) % GNSTG, (it + 2) * 64);

        const uint32_t sa = smb + (uint32_t)(stg * GSTAGE_BYTES);
        const uint32_t sb = sa + 128u * 144u;

#pragma unroll
        for (int ks = 0; ks < 4; ks++) {
            const uint32_t khb = (uint32_t)(ks * 16 * 2);
            uint32_t af[2][4];
            ldsm_x4(af[0], sa + a_off[0] + khb);
            ldsm_x4(af[1], sa + a_off[1] + khb);
            uint32_t bf[4][4];
#pragma unroll
            for (int nip = 0; nip < 4; nip++)
                ldsm_x4(bf[nip], sb + b_off[nip] + khb);
#pragma unroll
            for (int mi = 0; mi < 2; mi++)
#pragma unroll
                for (int nip = 0; nip < 4; nip++) {
                    mma_f16(acc[mi][2 * nip],     af[mi], bf[nip]);
                    mma_f16(acc[mi][2 * nip + 1], af[mi], bf[nip] + 2);
                }
        }
        stg = (stg + 1) % GNSTG;
    }

    const int row0 = blockIdx.y * 128 + wm;
    const int col0 = blockIdx.x * 128 + wn;
#pragma unroll
    for (int mi = 0; mi < 2; mi++) {
        int r = row0 + mi * 16 + g;
#pragma unroll
        for (int ni = 0; ni < 8; ni++) {
            int c = col0 + ni * 8 + t * 2;
            if (Ch) {
                *reinterpret_cast<uint32_t*>(Ch + (size_t)r * N + c) =
                    packh2(acc[mi][ni][0], acc[mi][ni][1]);
                *reinterpret_cast<uint32_t*>(Ch + (size_t)(r + 8) * N + c) =
                    packh2(acc[mi][ni][2], acc[mi][ni][3]);
            } else {
                float b0 = 0.f, b1 = 0.f;
                if (bias) { b0 = bias[c]; b1 = bias[c + 1]; }
                *reinterpret_cast<float2*>(Cf + (size_t)r * N + c) =
                    make_float2(acc[mi][ni][0] + b0, acc[mi][ni][1] + b1);
                *reinterpret_cast<float2*>(Cf + (size_t)(r + 8) * N + c) =
                    make_float2(acc[mi][ni][2] + b0, acc[mi][ni][3] + b1);
            }
        }
    }
}

// ---------------------------------------------------------------------------
// fp16 flash attention. Q-tile 128, KV-tile 64, 8 warps (16 Q rows each).
// P register-resident; ldmatrix everywhere; 3-stage KV ring, one barrier
// per KV tile, prefetch distance 2.
// NEW: softmax entirely in base-2 — Q is pre-scaled by 0.125*log2(e), so
// every exponential is a bare exp2f (single MUFU EX2, no companion FMUL).
// ---------------------------------------------------------------------------
#define ASTRH 72
#define BLKQ 128
#define KVSTG_BYTES (2 * 64 * ASTRH * 2)   // K+V per stage = 18432
#define KVNSTG 3
#define ATTN_SMEM_BYTES (BLKQ * ASTRH * 2 + KVNSTG * KVSTG_BYTES)

__global__ void __launch_bounds__(256)
attn_f16_kernel(const __half* __restrict__ qkv, __half* __restrict__ out)
{
    extern __shared__ char asm_[];
    __half* sQ = (__half*)asm_;
    const uint32_t sQb  = smem_u32(sQ);
    const uint32_t sKVb = sQb + BLKQ * ASTRH * 2;

    const int tid = threadIdx.x;
    const int lane = tid & 31;
    const int warp = tid >> 5;
    const int g = lane >> 2;
    const int t = lane & 3;
    const int m0 = warp * 16;

    const int qt = (int)(gridDim.x - 1) - (int)blockIdx.x;  // heavy first
    const int bh = blockIdx.y;
    const int b = bh >> 4, h = bh & 15;
    const __half* base = qkv + (size_t)b * LSEQ * QKVN + h * HDIM;
    const int q0 = qt * BLKQ;
    const int nkv = 2 * qt + 2;

    auto load_kv = [&](int kt, int stg) {
        uint32_t kb = sKVb + (uint32_t)(stg * KVSTG_BYTES);
        uint32_t vb = kb + 64u * ASTRH * 2u;
        const int k0 = kt * 64;
#pragma unroll
        for (int p = 0; p < 2; p++) {
            int idx = tid + p * 256;
            int r = idx >> 3, c16 = idx & 7;
            const __half* rp = base + (size_t)(k0 + r) * QKVN + c16 * 8;
            cpa16(kb + (uint32_t)(r * 144 + c16 * 16), rp + DMODEL);
            cpa16(vb + (uint32_t)(r * 144 + c16 * 16), rp + 2 * DMODEL);
        }
        cpa_commit();
    };

    // Q load (own group), then KV stages 0 and 1
#pragma unroll
    for (int p = 0; p < 4; p++) {
        int idx = tid + p * 256;
        int r = idx >> 3, c16 = idx & 7;
        cpa16(sQb + (uint32_t)(r * 144 + c16 * 16),
              base + (size_t)(q0 + r) * QKVN + c16 * 8);
    }
    cpa_commit();
    load_kv(0, 0);
    if (nkv > 1) load_kv(1, 1);

    if (nkv > 1) cpa_wait<2>(); else cpa_wait<1>();   // Q landed
    __syncthreads();

    // Hoist Q fragments via ldmatrix, scaled by 0.125*log2(e) so the softmax
    // logits are in base-2 domain (exp2f only, no extra FMUL per exp).
    uint32_t aq[4][4];
    {
        uint32_t q_off = (uint32_t)(((m0 + (lane & 15)) * ASTRH +
                                     ((lane >> 4) << 3)) * 2);
        const __half2 sc = __float2half2_rn(0.125f * 1.44269504f);
#pragma unroll
        for (int ks = 0; ks < 4; ks++) {
            ldsm_x4(aq[ks], sQb + q_off + (uint32_t)(ks * 16 * 2));
#pragma unroll
            for (int q = 0; q < 4; q++) {
                __half2 v = __hmul2(*reinterpret_cast<__half2*>(&aq[ks][q]), sc);
                aq[ks][q] = *reinterpret_cast<uint32_t*>(&v);
            }
        }
    }

    // K-fragment ldmatrix lane offset
    uint32_t k_off[4];
#pragma unroll
    for (int nip = 0; nip < 4; nip++)
        k_off[nip] = (uint32_t)(((nip * 16 + ((lane >> 4) << 3) +
                                  (lane & 7)) * ASTRH +
                                 (((lane >> 3) & 1) << 3)) * 2);

    float o[8][4];
#pragma unroll
    for (int nt = 0; nt < 8; nt++)
#pragma unroll
        for (int q = 0; q < 4; q++) o[nt][q] = 0.f;
    float mr0 = -1e30f, mr1 = -1e30f, l0 = 0.f, l1 = 0.f;

    const int row0g = q0 + m0 + g;
    const int row1g = row0g + 8;

    int stg = 0;
    for (int kt = 0; kt < nkv; kt++) {
        const int k0 = kt * 64;
        if (kt + 1 < nkv) cpa_wait<1>(); else cpa_wait<0>();
        __syncthreads();
        if (kt + 2 < nkv) load_kv(kt + 2, (stg + 2) % KVNSTG);

        const uint32_t kvb = sKVb + (uint32_t)(stg * KVSTG_BYTES);
        const uint32_t sVb = kvb + 64u * ASTRH * 2u;

        // S = (Q*scale*log2e) @ K^T : 16x64 per warp, 32 MMAs
        float s[8][4];
#pragma unroll
        for (int nt = 0; nt < 8; nt++)
#pragma unroll
            for (int q = 0; q < 4; q++) s[nt][q] = 0.f;

#pragma unroll
        for (int ks = 0; ks < 4; ks++) {
            const uint32_t khb = (uint32_t)(ks * 16 * 2);
#pragma unroll
            for (int nip = 0; nip < 4; nip++) {
                uint32_t bf[4];
                ldsm_x4(bf, kvb + k_off[nip] + khb);
                mma_f16(s[2 * nip],     aq[ks], bf);
                mma_f16(s[2 * nip + 1], aq[ks], bf + 2);
            }
        }

        // Causal mask (diagonal tiles only)
        if (kt >= 2 * qt) {
#pragma unroll
            for (int nt = 0; nt < 8; nt++) {
                int cb = k0 + nt * 8 + 2 * t;
#pragma unroll
                for (int q = 0; q < 2; q++) {
                    if (cb + q > row0g) s[nt][q] = -1e30f;
                    if (cb + q > row1g) s[nt][2 + q] = -1e30f;
                }
            }
        }

        // Online softmax, base-2 (rows g and g+8; quad-reduce over t lanes)
        float mt0 = -1e30f, mt1 = -1e30f;
#pragma unroll
        for (int nt = 0; nt < 8; nt++) {
            mt0 = fmaxf(mt0, fmaxf(s[nt][0], s[nt][1]));
            mt1 = fmaxf(mt1, fmaxf(s[nt][2], s[nt][3]));
        }
        mt0 = fmaxf(mt0, __shfl_xor_sync(0xffffffffu, mt0, 1));
        mt0 = fmaxf(mt0, __shfl_xor_sync(0xffffffffu, mt0, 2));
        mt1 = fmaxf(mt1, __shfl_xor_sync(0xffffffffu, mt1, 1));
        mt1 = fmaxf(mt1, __shfl_xor_sync(0xffffffffu, mt1, 2));

        float mn0 = fmaxf(mr0, mt0), mn1 = fmaxf(mr1, mt1);
        float cr0 = exp2f(mr0 - mn0), cr1 = exp2f(mr1 - mn1);
        mr0 = mn0; mr1 = mn1;

        float rs0 = 0.f, rs1 = 0.f;
#pragma unroll
        for (int nt = 0; nt < 8; nt++) {
            s[nt][0] = exp2f(s[nt][0] - mn0);
            s[nt][1] = exp2f(s[nt][1] - mn0);
            s[nt][2] = exp2f(s[nt][2] - mn1);
            s[nt][3] = exp2f(s[nt][3] - mn1);
            rs0 += s[nt][0] + s[nt][1];
            rs1 += s[nt][2] + s[nt][3];
        }
        rs0 += __shfl_xor_sync(0xffffffffu, rs0, 1);
        rs0 += __shfl_xor_sync(0xffffffffu, rs0, 2);
        rs1 += __shfl_xor_sync(0xffffffffu, rs1, 1);
        rs1 += __shfl_xor_sync(0xffffffffu, rs1, 2);
        l0 = l0 * cr0 + rs0;
        l1 = l1 * cr1 + rs1;

#pragma unroll
        for (int nt = 0; nt < 8; nt++) {
            o[nt][0] *= cr0; o[nt][1] *= cr0;
            o[nt][2] *= cr1; o[nt][3] *= cr1;
        }

        // Pack P fragments in registers
        uint32_t ap[4][4];
#pragma unroll
        for (int ks = 0; ks < 4; ks++) {
            ap[ks][0] = packh2(s[2 * ks][0], s[2 * ks][1]);
            ap[ks][1] = packh2(s[2 * ks][2], s[2 * ks][3]);
            ap[ks][2] = packh2(s[2 * ks + 1][0], s[2 * ks + 1][1]);
            ap[ks][3] = packh2(s[2 * ks + 1][2], s[2 * ks + 1][3]);
        }

        // O += P @ V, V frags via ldmatrix.x4.trans
#pragma unroll
        for (int ks = 0; ks < 4; ks++) {
#pragma unroll
            for (int ntp = 0; ntp < 4; ntp++) {
                uint32_t bv[4];
                uint32_t vaddr = sVb +
                    (uint32_t)(((16 * ks + (lane & 15)) * ASTRH +
                                ntp * 16 + ((lane >> 4) << 3)) * 2);
                ldsm_x4_t(bv, vaddr);
                mma_f16(o[2 * ntp],     ap[ks], bv);
                mma_f16(o[2 * ntp + 1], ap[ks], bv + 2);
            }
        }
        stg = (stg + 1) % KVNSTG;
    }

    // Epilogue: normalize, write fp16 (B*L, D)
    float inv0 = 1.0f / l0, inv1 = 1.0f / l1;
    __half* ob0 = out + (size_t)(b * LSEQ + row0g) * DMODEL + h * HDIM + 2 * t;
    __half* ob1 = out + (size_t)(b * LSEQ + row1g) * DMODEL + h * HDIM + 2 * t;
#pragma unroll
    for (int nt = 0; nt < 8; nt++) {
        *reinterpret_cast<uint32_t*>(ob0 + nt * 8) =
            packh2(o[nt][0] * inv0, o[nt][1] * inv0);
        *reinterpret_cast<uint32_t*>(ob1 + nt * 8) =
            packh2(o[nt][2] * inv1, o[nt][3] * inv1);
    }
}

// ---------------------------------------------------------------------------
extern "C" void kernel_launch(void* const* d_in, const int* in_sizes, int n_in,
                              void* d_out, int out_size)
{
    (void)in_sizes; (void)n_in; (void)out_size;
    const float* x      = (const float*)d_in[0];
    // d_in[1] = attn_mask (always causal triu(k=1); implemented directly)
    const float* w_qkv  = (const float*)d_in[2];
    const float* w_proj = (const float*)d_in[3];
    const float* b_proj = (const float*)d_in[4];
    float* out = (float*)d_out;

    __half *xh, *wqkvT, *wprojT, *qkvh, *attnh;
    cudaGetSymbolAddress((void**)&xh, g_x_h);
    cudaGetSymbolAddress((void**)&wqkvT, g_wqkvT_h);
    cudaGetSymbolAddress((void**)&wprojT, g_wprojT_h);
    cudaGetSymbolAddress((void**)&qkvh, g_qkv_h);
    cudaGetSymbolAddress((void**)&attnh, g_attn_h);

    cudaFuncSetAttribute(gemm_f16_kernel,
                         cudaFuncAttributeMaxDynamicSharedMemorySize,
                         GEMM_SMEM_BYTES);
    cudaFuncSetAttribute(attn_f16_kernel,
                         cudaFuncAttributeMaxDynamicSharedMemorySize,
                         ATTN_SMEM_BYTES);

    // 0) Fused pre-pass: one launch for x cvt + both weight transposes
    {
        prepass_kernel<<<NB_X + NB_WQ + NB_WP, 256>>>(
            x, xh, w_qkv, wqkvT, w_proj, wprojT);
    }

    // 1) QKV GEMM: (8192,1024) @ (1024,3072), fp16 out
    {
        dim3 grid(QKVN / 128, MROWS / 128);
        gemm_f16_kernel<<<grid, 256, GEMM_SMEM_BYTES>>>(
            xh, wqkvT, nullptr, qkvh, MROWS, QKVN, DMODEL, nullptr);
    }
    // 2) Causal flash attention (fp16 MMA, register P, base-2 softmax)
    {
        dim3 grid(LSEQ / BLKQ, BB * NH);
        attn_f16_kernel<<<grid, 256, ATTN_SMEM_BYTES>>>(qkvh, attnh);
    }
    // 3) Output projection + bias: (8192,1024) @ (1024,1024), fp32 out
    {
        dim3 grid(DMODEL / 128, MROWS / 128);
        gemm_f16_kernel<<<grid, 256, GEMM_SMEM_BYTES>>>(
            attnh, wprojT, out, nullptr, MROWS, DMODEL, DMODEL, b_proj);
    }
}